// round 1
// baseline (speedup 1.0000x reference)
#include <cuda_runtime.h>
#include <cuda_bf16.h>

// Problem geometry (fixed by reference setup_inputs)
#define DD 128
#define HH 160
#define WW 192
#define NVOX (DD * HH * WW)           // 3,932,160
#define NCH 5
#define RAD 4                          // 9-tap box, radius 4

// H pass chunking
#define HCH 4
#define HL  (HH / HCH)                 // 40
// D pass chunking
#define DCH 4
#define DL  (DD / DCH)                 // 32
#define NPART (HH * DCH)               // 640 partials

// Scratch (allocation-free rule: __device__ globals)
__device__ float g_bufA[NCH][NVOX];
__device__ float g_bufB[NCH][NVOX];
__device__ float g_partials[NPART];

// ---------------------------------------------------------------------------
// Pass 1: build the 5 channels on the fly and box-sum along W (contiguous).
// One block per (d,h) row, 192 threads = W.
// ---------------------------------------------------------------------------
__global__ __launch_bounds__(WW) void ncc_pass_w(const float* __restrict__ I,
                                                 const float* __restrict__ J) {
    const int row  = blockIdx.x;          // d*HH + h, 0..20479
    const int base = row * WW;
    const int w    = threadIdx.x;

    __shared__ float sI[WW];
    __shared__ float sJ[WW];
    sI[w] = I[base + w];
    sJ[w] = J[base + w];
    __syncthreads();

    float s0 = 0.f, s1 = 0.f, s2 = 0.f, s3 = 0.f, s4 = 0.f;
#pragma unroll
    for (int t = -RAD; t <= RAD; t++) {
        int x = w + t;
        if (x >= 0 && x < WW) {
            float i = sI[x];
            float j = sJ[x];
            s0 += i;
            s1 += j;
            s2 += i * i;
            s3 += j * j;
            s4 += i * j;
        }
    }
    g_bufA[0][base + w] = s0;
    g_bufA[1][base + w] = s1;
    g_bufA[2][base + w] = s2;
    g_bufA[3][base + w] = s3;
    g_bufA[4][base + w] = s4;
}

// ---------------------------------------------------------------------------
// Pass 2: box-sum along H. Sliding add/subtract window per thread.
// Grid: (D, NCH, HCH); block: 192 threads = W (coalesced).
// ---------------------------------------------------------------------------
__global__ __launch_bounds__(WW) void ncc_pass_h() {
    const int d  = blockIdx.x;
    const int c  = blockIdx.y;
    const int h0 = blockIdx.z * HL;
    const int w  = threadIdx.x;

    const float* __restrict__ in = &g_bufA[c][(size_t)d * HH * WW + w];
    float* __restrict__ out      = &g_bufB[c][(size_t)d * HH * WW + w];

    // Prime window [h0-4 .. h0+3]
    float sum = 0.f;
#pragma unroll
    for (int h = h0 - RAD; h < h0 + RAD; h++)
        if (h >= 0 && h < HH) sum += in[h * WW];

    for (int h = h0; h < h0 + HL; h++) {
        if (h + RAD < HH) sum += in[(h + RAD) * WW];
        out[h * WW] = sum;
        if (h - RAD >= 0) sum -= in[(h - RAD) * WW];
    }
}

// ---------------------------------------------------------------------------
// Pass 3: box-sum along D (sliding window, all 5 channels) fused with the
// per-voxel cc computation and a block reduction into partials.
// Grid: (H, DCH); block: 192 threads = W.
// ---------------------------------------------------------------------------
__global__ __launch_bounds__(WW) void ncc_pass_d(float inv_ws) {
    const int h  = blockIdx.x;
    const int d0 = blockIdx.y * DL;
    const int w  = threadIdx.x;
    const size_t base   = (size_t)h * WW + w;
    const size_t stride = (size_t)HH * WW;

    float s[NCH] = {0.f, 0.f, 0.f, 0.f, 0.f};

    // Prime window [d0-4 .. d0+3]
#pragma unroll
    for (int d = d0 - RAD; d < d0 + RAD; d++) {
        if (d >= 0 && d < DD) {
#pragma unroll
            for (int c = 0; c < NCH; c++)
                s[c] += g_bufB[c][base + (size_t)d * stride];
        }
    }

    float acc = 0.f;
    for (int d = d0; d < d0 + DL; d++) {
        if (d + RAD < DD) {
#pragma unroll
            for (int c = 0; c < NCH; c++)
                s[c] += g_bufB[c][base + (size_t)(d + RAD) * stride];
        }
        // cc at this voxel
        float Is = s[0], Js = s[1], I2 = s[2], J2 = s[3], IJ = s[4];
        float cross = IJ - Js * inv_ws * Is;
        float Ivar  = I2 - Is * inv_ws * Is;
        float Jvar  = J2 - Js * inv_ws * Js;
        float cc    = cross * cross / (Ivar * Jvar + 1e-5f);
        acc += cc;

        if (d - RAD >= 0) {
#pragma unroll
            for (int c = 0; c < NCH; c++)
                s[c] -= g_bufB[c][base + (size_t)(d - RAD) * stride];
        }
    }

    // Block reduction (192 threads)
    __shared__ float red[WW];
    red[w] = acc;
    __syncthreads();
    for (int off = 128; off > 0; off >>= 1) {
        if (w < off && w + off < WW) red[w] += red[w + off];
        __syncthreads();
    }
    if (w == 0) g_partials[blockIdx.x * DCH + blockIdx.y] = red[0];
}

// ---------------------------------------------------------------------------
// Pass 4: final reduction of 640 partials, write scalar loss.
// ---------------------------------------------------------------------------
__global__ __launch_bounds__(256) void ncc_final(float* __restrict__ out) {
    __shared__ double red[256];
    const int t = threadIdx.x;
    double acc = 0.0;
    for (int i = t; i < NPART; i += 256) acc += (double)g_partials[i];
    red[t] = acc;
    __syncthreads();
    for (int off = 128; off > 0; off >>= 1) {
        if (t < off) red[t] += red[t + off];
        __syncthreads();
    }
    if (t == 0) out[0] = (float)(1.0 - red[0] / (double)NVOX);
}

// ---------------------------------------------------------------------------
extern "C" void kernel_launch(void* const* d_in, const int* in_sizes, int n_in,
                              void* d_out, int out_size) {
    const float* y_true = (const float*)d_in[0];
    const float* y_pred = (const float*)d_in[1];
    float* out = (float*)d_out;

    const float inv_ws = 1.0f / 729.0f;  // 9*9*9

    ncc_pass_w<<<DD * HH, WW>>>(y_true, y_pred);

    dim3 gh(DD, NCH, HCH);
    ncc_pass_h<<<gh, WW>>>();

    dim3 gd(HH, DCH);
    ncc_pass_d<<<gd, WW>>>(inv_ws);

    ncc_final<<<1, 256>>>(out);
}

// round 3
// speedup vs baseline: 1.2438x; 1.2438x over previous
#include <cuda_runtime.h>
#include <cuda_bf16.h>

// Problem geometry (fixed by reference setup_inputs)
#define DD 128
#define HH 160
#define WW 192
#define NVOX (DD * HH * WW)            // 3,932,160
#define NCH 5
#define RAD 4                           // 9-tap box, radius 4

// WH-pass chunking along H
#define HCH 4
#define HL  (HH / HCH)                  // 40
// D-pass chunking along D
#define DCH 4
#define DL  (DD / DCH)                  // 32
#define NBLK_D (HH * DCH)               // 640 blocks -> 640 partials

// Scratch (allocation-free rule: __device__ globals)
__device__ float g_buf[NCH][NVOX];      // W+H box-summed channels
__device__ float g_partials[NBLK_D];
__device__ unsigned int g_count = 0;

// ---------------------------------------------------------------------------
// Kernel 1: build channels on the fly, box-sum along W (smem row + 9 taps)
// and along H (per-thread sliding window with a 9-deep smem ring).
// Grid: (DD, HCH); block: 192 threads = W.
// ---------------------------------------------------------------------------
__global__ __launch_bounds__(WW) void ncc_pass_wh(const float* __restrict__ I,
                                                  const float* __restrict__ J) {
    const int d  = blockIdx.x;
    const int h0 = blockIdx.y * HL;
    const int w  = threadIdx.x;

    __shared__ float sI[2][WW];
    __shared__ float sJ[2][WW];
    __shared__ float ring[9][NCH][WW];   // W-sums of the last 9 rows (per thread col)

    float a0 = 0.f, a1 = 0.f, a2 = 0.f, a3 = 0.f, a4 = 0.f;  // H sliding accum
    int buf = 0;
    const size_t dbase = (size_t)d * HH * WW;

    for (int cnt = 0; cnt < HL + 2 * RAD; cnt++) {
        const int hr = h0 - RAD + cnt;       // input row entering the window
        float w0 = 0.f, w1 = 0.f, w2 = 0.f, w3 = 0.f, w4 = 0.f;

        if (hr >= 0 && hr < HH) {            // block-uniform condition
            sI[buf][w] = I[dbase + (size_t)hr * WW + w];
            sJ[buf][w] = J[dbase + (size_t)hr * WW + w];
            __syncthreads();
#pragma unroll
            for (int t = -RAD; t <= RAD; t++) {
                int x = w + t;
                if (x >= 0 && x < WW) {
                    float i = sI[buf][x];
                    float j = sJ[buf][x];
                    w0 += i;
                    w1 += j;
                    w2 = fmaf(i, i, w2);
                    w3 = fmaf(j, j, w3);
                    w4 = fmaf(i, j, w4);
                }
            }
        }
        // window gains row hr
        a0 += w0; a1 += w1; a2 += w2; a3 += w3; a4 += w4;

        const int slot = cnt % 9;
        ring[slot][0][w] = w0;
        ring[slot][1][w] = w1;
        ring[slot][2][w] = w2;
        ring[slot][3][w] = w3;
        ring[slot][4][w] = w4;

        const int h = hr - RAD;              // output row with full window
        if (h >= h0) {
            const size_t o = dbase + (size_t)h * WW + w;
            g_buf[0][o] = a0;
            g_buf[1][o] = a1;
            g_buf[2][o] = a2;
            g_buf[3][o] = a3;
            g_buf[4][o] = a4;
        }
        // row (hr-8) leaves the window before next iteration
        if (cnt >= 8) {
            const int os = (cnt + 1) % 9;    // == (cnt-8) % 9
            a0 -= ring[os][0][w];
            a1 -= ring[os][1][w];
            a2 -= ring[os][2][w];
            a3 -= ring[os][3][w];
            a4 -= ring[os][4][w];
        }
        buf ^= 1;
    }
}

// ---------------------------------------------------------------------------
// Kernel 2: box-sum along D (sliding window over 5 channels), fused with the
// per-voxel cc computation, block reduction, and last-block final reduction.
// Grid: (HH, DCH); block: 192 threads = W.
// ---------------------------------------------------------------------------
__global__ __launch_bounds__(WW) void ncc_pass_d(float* __restrict__ out) {
    const int h  = blockIdx.x;
    const int d0 = blockIdx.y * DL;
    const int w  = threadIdx.x;
    const size_t base   = (size_t)h * WW + w;
    const size_t stride = (size_t)HH * WW;
    const float inv_ws  = 1.0f / 729.0f;

    float s0 = 0.f, s1 = 0.f, s2 = 0.f, s3 = 0.f, s4 = 0.f;

    // Prime window [d0-4 .. d0+3]
#pragma unroll
    for (int d = d0 - RAD; d < d0 + RAD; d++) {
        if (d >= 0 && d < DD) {
            const size_t o = base + (size_t)d * stride;
            s0 += g_buf[0][o];
            s1 += g_buf[1][o];
            s2 += g_buf[2][o];
            s3 += g_buf[3][o];
            s4 += g_buf[4][o];
        }
    }

    float acc = 0.f;
    for (int d = d0; d < d0 + DL; d++) {
        if (d + RAD < DD) {
            const size_t o = base + (size_t)(d + RAD) * stride;
            s0 += g_buf[0][o];
            s1 += g_buf[1][o];
            s2 += g_buf[2][o];
            s3 += g_buf[3][o];
            s4 += g_buf[4][o];
        }
        // cc at this voxel
        float cross = s4 - s1 * inv_ws * s0;
        float Ivar  = s2 - s0 * inv_ws * s0;
        float Jvar  = s3 - s1 * inv_ws * s1;
        float cc    = cross * cross / (Ivar * Jvar + 1e-5f);
        acc += cc;

        if (d - RAD >= 0) {
            const size_t o = base + (size_t)(d - RAD) * stride;
            s0 -= g_buf[0][o];
            s1 -= g_buf[1][o];
            s2 -= g_buf[2][o];
            s3 -= g_buf[3][o];
            s4 -= g_buf[4][o];
        }
    }

    // --- block reduction (192 threads = 6 warps) ---
#pragma unroll
    for (int off = 16; off > 0; off >>= 1)
        acc += __shfl_down_sync(0xFFFFFFFFu, acc, off);

    __shared__ float warpsum[6];
    __shared__ bool  s_last;
    if ((w & 31) == 0) warpsum[w >> 5] = acc;
    __syncthreads();

    if (w == 0) {
        float b = warpsum[0] + warpsum[1] + warpsum[2] +
                  warpsum[3] + warpsum[4] + warpsum[5];
        g_partials[blockIdx.x * DCH + blockIdx.y] = b;
        __threadfence();
        unsigned t = atomicAdd(&g_count, 1u);
        s_last = (t == NBLK_D - 1);
    }
    __syncthreads();

    // --- last block: deterministic final reduction in double ---
    if (s_last) {
        __threadfence();
        double a = 0.0;
        for (int i = w; i < NBLK_D; i += WW) a += (double)g_partials[i];
#pragma unroll
        for (int off = 16; off > 0; off >>= 1)
            a += __shfl_down_sync(0xFFFFFFFFu, a, off);

        __shared__ double dsum[6];
        if ((w & 31) == 0) dsum[w >> 5] = a;
        __syncthreads();
        if (w == 0) {
            double tot = dsum[0] + dsum[1] + dsum[2] + dsum[3] + dsum[4] + dsum[5];
            out[0] = (float)(1.0 - tot / (double)NVOX);
            g_count = 0;   // reset for next graph replay
        }
    }
}

// ---------------------------------------------------------------------------
extern "C" void kernel_launch(void* const* d_in, const int* in_sizes, int n_in,
                              void* d_out, int out_size) {
    const float* y_true = (const float*)d_in[0];
    const float* y_pred = (const float*)d_in[1];
    float* out = (float*)d_out;

    dim3 gwh(DD, HCH);
    ncc_pass_wh<<<gwh, WW>>>(y_true, y_pred);

    dim3 gd(HH, DCH);
    ncc_pass_d<<<gd, WW>>>(out);
}

// round 4
// speedup vs baseline: 1.6170x; 1.3000x over previous
#include <cuda_runtime.h>
#include <cuda_bf16.h>

// Problem geometry (fixed by reference setup_inputs)
#define DD 128
#define HH 160
#define WW 192
#define NVOX (DD * HH * WW)            // 3,932,160
#define NCH 5
#define RAD 4                           // 9-tap box, radius 4

// WH-pass chunking along H
#define HCH 8
#define HL  (HH / HCH)                  // 20
// D-pass chunking along D
#define DCH 8
#define DL  (DD / DCH)                  // 16
#define NBLK_D (HH * DCH)               // 1280 blocks -> 1280 partials

// Scratch (allocation-free rule: __device__ globals)
__device__ float g_buf[NCH][NVOX];      // W+H box-summed channels
__device__ float g_partials[NBLK_D];
__device__ unsigned int g_count = 0;

// ---------------------------------------------------------------------------
// Kernel 1: build channels on the fly, box-sum along W (smem row + 9 taps)
// and along H (per-thread sliding window with a 9-deep smem ring).
// Register-prefetch of the next row hides GMEM latency behind the taps.
// Grid: (DD, HCH); block: 192 threads = W.
// ---------------------------------------------------------------------------
__global__ __launch_bounds__(WW) void ncc_pass_wh(const float* __restrict__ I,
                                                  const float* __restrict__ J) {
    const int d  = blockIdx.x;
    const int h0 = blockIdx.y * HL;
    const int w  = threadIdx.x;
    const size_t dbase = (size_t)d * HH * WW;

    __shared__ float sI[2][WW];
    __shared__ float sJ[2][WW];
    __shared__ float ring[9][NCH][WW];   // W-sums of the last 9 rows (per thread col)

    float a0 = 0.f, a1 = 0.f, a2 = 0.f, a3 = 0.f, a4 = 0.f;  // H sliding accum
    int buf = 0;

    const int NIT = HL + 2 * RAD;        // 28

    // Preload first row (zero-filled when outside the volume)
    float rI = 0.f, rJ = 0.f;
    {
        int hr = h0 - RAD;
        if (hr >= 0 && hr < HH) {
            rI = I[dbase + (size_t)hr * WW + w];
            rJ = J[dbase + (size_t)hr * WW + w];
        }
    }

    for (int cnt = 0; cnt < NIT; cnt++) {
        sI[buf][w] = rI;
        sJ[buf][w] = rJ;
        __syncthreads();

        // Prefetch next row while taps compute (hides DRAM latency)
        rI = 0.f; rJ = 0.f;
        {
            int hn = h0 - RAD + cnt + 1;
            if (cnt + 1 < NIT && hn >= 0 && hn < HH) {
                rI = I[dbase + (size_t)hn * WW + w];
                rJ = J[dbase + (size_t)hn * WW + w];
            }
        }

        // 9-tap W box sums of the 5 channels (zeros pad naturally)
        float w0 = 0.f, w1 = 0.f, w2 = 0.f, w3 = 0.f, w4 = 0.f;
#pragma unroll
        for (int t = -RAD; t <= RAD; t++) {
            int x = w + t;
            if (x >= 0 && x < WW) {
                float i = sI[buf][x];
                float j = sJ[buf][x];
                w0 += i;
                w1 += j;
                w2 = fmaf(i, i, w2);
                w3 = fmaf(j, j, w3);
                w4 = fmaf(i, j, w4);
            }
        }

        // window gains this row
        a0 += w0; a1 += w1; a2 += w2; a3 += w3; a4 += w4;

        const int slot = cnt % 9;
        ring[slot][0][w] = w0;
        ring[slot][1][w] = w1;
        ring[slot][2][w] = w2;
        ring[slot][3][w] = w3;
        ring[slot][4][w] = w4;

        const int h = (h0 - RAD + cnt) - RAD;    // output row with full window
        if (h >= h0) {
            const size_t o = dbase + (size_t)h * WW + w;
            g_buf[0][o] = a0;
            g_buf[1][o] = a1;
            g_buf[2][o] = a2;
            g_buf[3][o] = a3;
            g_buf[4][o] = a4;
        }
        // row entering 9 iterations ago leaves the window
        if (cnt >= 8) {
            const int os = (cnt + 1) % 9;        // == (cnt-8) % 9
            a0 -= ring[os][0][w];
            a1 -= ring[os][1][w];
            a2 -= ring[os][2][w];
            a3 -= ring[os][3][w];
            a4 -= ring[os][4][w];
        }
        buf ^= 1;
    }
}

// ---------------------------------------------------------------------------
// Kernel 2: box-sum along D (sliding window over 5 channels), fused with the
// per-voxel cc computation, block reduction, and last-block final reduction.
// Grid: (HH, DCH); block: 192 threads = W.
// ---------------------------------------------------------------------------
__global__ __launch_bounds__(WW) void ncc_pass_d(float* __restrict__ out) {
    const int h  = blockIdx.x;
    const int d0 = blockIdx.y * DL;
    const int w  = threadIdx.x;
    const size_t base   = (size_t)h * WW + w;
    const size_t stride = (size_t)HH * WW;
    const float inv_ws  = 1.0f / 729.0f;

    float s0 = 0.f, s1 = 0.f, s2 = 0.f, s3 = 0.f, s4 = 0.f;

    // Prime window [d0-4 .. d0+3]
#pragma unroll
    for (int d = d0 - RAD; d < d0 + RAD; d++) {
        if (d >= 0 && d < DD) {
            const size_t o = base + (size_t)d * stride;
            s0 += g_buf[0][o];
            s1 += g_buf[1][o];
            s2 += g_buf[2][o];
            s3 += g_buf[3][o];
            s4 += g_buf[4][o];
        }
    }

    float acc = 0.f;
    for (int d = d0; d < d0 + DL; d++) {
        if (d + RAD < DD) {
            const size_t o = base + (size_t)(d + RAD) * stride;
            s0 += g_buf[0][o];
            s1 += g_buf[1][o];
            s2 += g_buf[2][o];
            s3 += g_buf[3][o];
            s4 += g_buf[4][o];
        }
        // cc at this voxel
        float cross = s4 - s1 * inv_ws * s0;
        float Ivar  = s2 - s0 * inv_ws * s0;
        float Jvar  = s3 - s1 * inv_ws * s1;
        float cc    = cross * cross / (Ivar * Jvar + 1e-5f);
        acc += cc;

        if (d - RAD >= 0) {
            const size_t o = base + (size_t)(d - RAD) * stride;
            s0 -= g_buf[0][o];
            s1 -= g_buf[1][o];
            s2 -= g_buf[2][o];
            s3 -= g_buf[3][o];
            s4 -= g_buf[4][o];
        }
    }

    // --- block reduction (192 threads = 6 warps) ---
#pragma unroll
    for (int off = 16; off > 0; off >>= 1)
        acc += __shfl_down_sync(0xFFFFFFFFu, acc, off);

    __shared__ float warpsum[6];
    __shared__ bool  s_last;
    if ((w & 31) == 0) warpsum[w >> 5] = acc;
    __syncthreads();

    if (w == 0) {
        float b = warpsum[0] + warpsum[1] + warpsum[2] +
                  warpsum[3] + warpsum[4] + warpsum[5];
        g_partials[blockIdx.x * DCH + blockIdx.y] = b;
        __threadfence();
        unsigned t = atomicAdd(&g_count, 1u);
        s_last = (t == NBLK_D - 1);
    }
    __syncthreads();

    // --- last block: deterministic final reduction in double ---
    if (s_last) {
        __threadfence();
        double a = 0.0;
        for (int i = w; i < NBLK_D; i += WW) a += (double)g_partials[i];
#pragma unroll
        for (int off = 16; off > 0; off >>= 1)
            a += __shfl_down_sync(0xFFFFFFFFu, a, off);

        __shared__ double dsum[6];
        if ((w & 31) == 0) dsum[w >> 5] = a;
        __syncthreads();
        if (w == 0) {
            double tot = dsum[0] + dsum[1] + dsum[2] + dsum[3] + dsum[4] + dsum[5];
            out[0] = (float)(1.0 - tot / (double)NVOX);
            g_count = 0;   // reset for next graph replay
        }
    }
}

// ---------------------------------------------------------------------------
extern "C" void kernel_launch(void* const* d_in, const int* in_sizes, int n_in,
                              void* d_out, int out_size) {
    const float* y_true = (const float*)d_in[0];
    const float* y_pred = (const float*)d_in[1];
    float* out = (float*)d_out;

    dim3 gwh(DD, HCH);
    ncc_pass_wh<<<gwh, WW>>>(y_true, y_pred);

    dim3 gd(HH, DCH);
    ncc_pass_d<<<gd, WW>>>(out);
}

// round 5
// speedup vs baseline: 2.1385x; 1.3225x over previous
#include <cuda_runtime.h>
#include <cuda_fp16.h>
#include <cuda_bf16.h>

// Problem geometry (fixed by reference setup_inputs)
#define DD 128
#define HH 160
#define WW 192
#define NVOX (DD * HH * WW)            // 3,932,160
#define RAD 4                           // 9-tap box, radius 4

// WH-pass chunking along H
#define HCH 8
#define HL  (HH / HCH)                  // 20
// D-pass chunking along D
#define DCH 8
#define DL  (DD / DCH)                  // 16
#define NBLK_D (HH * DCH)               // 1280 blocks -> 1280 partials

// Scratch (allocation-free rule: __device__ globals).
// fp16-packed WH box sums: g_p4 = (half2(I,J), half2(I2,J2)), g_pe = half(IJ).
__device__ uint2  g_p4[NVOX];
__device__ __half g_pe[NVOX];
__device__ float  g_partials[NBLK_D];
__device__ unsigned int g_count = 0;

// ---------------------------------------------------------------------------
// Kernel 1: build channels on the fly, box-sum along W (padded smem row, 9
// unconditional taps) and along H (per-thread sliding window, 9-deep smem
// ring). Register-prefetch of the next row hides GMEM latency. fp16 output.
// Grid: (DD, HCH); block: 192 threads = W.
// ---------------------------------------------------------------------------
__global__ __launch_bounds__(WW) void ncc_pass_wh(const float* __restrict__ I,
                                                  const float* __restrict__ J) {
    const int d  = blockIdx.x;
    const int h0 = blockIdx.y * HL;
    const int w  = threadIdx.x;
    const size_t dbase = (size_t)d * HH * WW;

    __shared__ float sI[2][WW + 2 * RAD];
    __shared__ float sJ[2][WW + 2 * RAD];
    __shared__ float ring[9][5][WW];     // W-sums of the last 9 rows

    // zero the pads once (protected by the first __syncthreads below)
    if (w < 2 * RAD) {
        int p = (w < RAD) ? w : (WW + w);   // 0..3 and WW+4..WW+7
        sI[0][p] = 0.f; sI[1][p] = 0.f;
        sJ[0][p] = 0.f; sJ[1][p] = 0.f;
    }

    float a0 = 0.f, a1 = 0.f, a2 = 0.f, a3 = 0.f, a4 = 0.f;  // H sliding accum
    int buf = 0;
    const int NIT = HL + 2 * RAD;        // 28

    // Preload first row (zero-filled when outside the volume)
    float rI = 0.f, rJ = 0.f;
    {
        int hr = h0 - RAD;
        if (hr >= 0 && hr < HH) {
            rI = I[dbase + (size_t)hr * WW + w];
            rJ = J[dbase + (size_t)hr * WW + w];
        }
    }

    for (int cnt = 0; cnt < NIT; cnt++) {
        sI[buf][w + RAD] = rI;
        sJ[buf][w + RAD] = rJ;
        __syncthreads();

        // Prefetch next row while taps compute (hides DRAM latency)
        rI = 0.f; rJ = 0.f;
        {
            int hn = h0 - RAD + cnt + 1;
            if (cnt + 1 < NIT && hn >= 0 && hn < HH) {
                rI = I[dbase + (size_t)hn * WW + w];
                rJ = J[dbase + (size_t)hn * WW + w];
            }
        }

        // 9 unconditional taps (pads are zero)
        float w0 = 0.f, w1 = 0.f, w2 = 0.f, w3 = 0.f, w4 = 0.f;
#pragma unroll
        for (int t = 0; t < 9; t++) {
            float i = sI[buf][w + t];
            float j = sJ[buf][w + t];
            w0 += i;
            w1 += j;
            w2 = fmaf(i, i, w2);
            w3 = fmaf(j, j, w3);
            w4 = fmaf(i, j, w4);
        }

        // window gains this row
        a0 += w0; a1 += w1; a2 += w2; a3 += w3; a4 += w4;

        const int slot = cnt % 9;
        ring[slot][0][w] = w0;
        ring[slot][1][w] = w1;
        ring[slot][2][w] = w2;
        ring[slot][3][w] = w3;
        ring[slot][4][w] = w4;

        const int h = (h0 - RAD + cnt) - RAD;    // output row with full window
        if (h >= h0) {
            const size_t o = dbase + (size_t)h * WW + w;
            __half2 h01 = __floats2half2_rn(a0, a1);
            __half2 h23 = __floats2half2_rn(a2, a3);
            uint2 p;
            p.x = *reinterpret_cast<const unsigned int*>(&h01);
            p.y = *reinterpret_cast<const unsigned int*>(&h23);
            g_p4[o] = p;
            g_pe[o] = __float2half_rn(a4);
        }
        // row entering 9 iterations ago leaves the window
        if (cnt >= 8) {
            const int os = (cnt + 1) % 9;        // == (cnt-8) % 9
            a0 -= ring[os][0][w];
            a1 -= ring[os][1][w];
            a2 -= ring[os][2][w];
            a3 -= ring[os][3][w];
            a4 -= ring[os][4][w];
        }
        buf ^= 1;
    }
}

// ---------------------------------------------------------------------------
// Kernel 2: box-sum along D (fp32 sliding window over the fp16 channels),
// fused with the per-voxel cc, block reduction, and last-block final sum.
// Grid: (HH, DCH); block: 192 threads = W.
// ---------------------------------------------------------------------------
__device__ __forceinline__ void load5(size_t o, float& v0, float& v1,
                                      float& v2, float& v3, float& v4) {
    uint2 p = g_p4[o];
    __half2 h01 = *reinterpret_cast<const __half2*>(&p.x);
    __half2 h23 = *reinterpret_cast<const __half2*>(&p.y);
    float2 f01 = __half22float2(h01);
    float2 f23 = __half22float2(h23);
    v0 = f01.x; v1 = f01.y; v2 = f23.x; v3 = f23.y;
    v4 = __half2float(g_pe[o]);
}

__global__ __launch_bounds__(WW) void ncc_pass_d(float* __restrict__ out) {
    const int h  = blockIdx.x;
    const int d0 = blockIdx.y * DL;
    const int w  = threadIdx.x;
    const size_t base   = (size_t)h * WW + w;
    const size_t stride = (size_t)HH * WW;
    const float inv_ws  = 1.0f / 729.0f;

    float s0 = 0.f, s1 = 0.f, s2 = 0.f, s3 = 0.f, s4 = 0.f;

    // Prime window [d0-4 .. d0+3]
#pragma unroll
    for (int d = d0 - RAD; d < d0 + RAD; d++) {
        if (d >= 0 && d < DD) {
            float v0, v1, v2, v3, v4;
            load5(base + (size_t)d * stride, v0, v1, v2, v3, v4);
            s0 += v0; s1 += v1; s2 += v2; s3 += v3; s4 += v4;
        }
    }

    float acc = 0.f;
    for (int d = d0; d < d0 + DL; d++) {
        if (d + RAD < DD) {
            float v0, v1, v2, v3, v4;
            load5(base + (size_t)(d + RAD) * stride, v0, v1, v2, v3, v4);
            s0 += v0; s1 += v1; s2 += v2; s3 += v3; s4 += v4;
        }
        // cc at this voxel
        float cross = s4 - s1 * inv_ws * s0;
        float Ivar  = s2 - s0 * inv_ws * s0;
        float Jvar  = s3 - s1 * inv_ws * s1;
        float cc    = cross * cross / (Ivar * Jvar + 1e-5f);
        acc += cc;

        if (d - RAD >= 0) {
            float v0, v1, v2, v3, v4;
            load5(base + (size_t)(d - RAD) * stride, v0, v1, v2, v3, v4);
            s0 -= v0; s1 -= v1; s2 -= v2; s3 -= v3; s4 -= v4;
        }
    }

    // --- block reduction (192 threads = 6 warps) ---
#pragma unroll
    for (int off = 16; off > 0; off >>= 1)
        acc += __shfl_down_sync(0xFFFFFFFFu, acc, off);

    __shared__ float warpsum[6];
    __shared__ bool  s_last;
    if ((w & 31) == 0) warpsum[w >> 5] = acc;
    __syncthreads();

    if (w == 0) {
        float b = warpsum[0] + warpsum[1] + warpsum[2] +
                  warpsum[3] + warpsum[4] + warpsum[5];
        g_partials[blockIdx.x * DCH + blockIdx.y] = b;
        __threadfence();
        unsigned t = atomicAdd(&g_count, 1u);
        s_last = (t == NBLK_D - 1);
    }
    __syncthreads();

    // --- last block: deterministic final reduction in double ---
    if (s_last) {
        __threadfence();
        double a = 0.0;
        for (int i = w; i < NBLK_D; i += WW) a += (double)g_partials[i];
#pragma unroll
        for (int off = 16; off > 0; off >>= 1)
            a += __shfl_down_sync(0xFFFFFFFFu, a, off);

        __shared__ double dsum[6];
        if ((w & 31) == 0) dsum[w >> 5] = a;
        __syncthreads();
        if (w == 0) {
            double tot = dsum[0] + dsum[1] + dsum[2] + dsum[3] + dsum[4] + dsum[5];
            out[0] = (float)(1.0 - tot / (double)NVOX);
            g_count = 0;   // reset for next graph replay
        }
    }
}

// ---------------------------------------------------------------------------
extern "C" void kernel_launch(void* const* d_in, const int* in_sizes, int n_in,
                              void* d_out, int out_size) {
    const float* y_true = (const float*)d_in[0];
    const float* y_pred = (const float*)d_in[1];
    float* out = (float*)d_out;

    dim3 gwh(DD, HCH);
    ncc_pass_wh<<<gwh, WW>>>(y_true, y_pred);

    dim3 gd(HH, DCH);
    ncc_pass_d<<<gd, WW>>>(out);
}